// round 11
// baseline (speedup 1.0000x reference)
#include <cuda_runtime.h>
#include <cstdint>

// Problem constants
#define BB 1024
#define TT 4096
#define LL 30
#define HH 32
#define PP 2

typedef unsigned long long u64;

// ---------------------------------------------------------------------------
// Accurate tanh (encoder/epilogue; abs err ~1e-7):
// tanh(x) = 1 - 2/(exp2(2*log2e*x)+1)
// ---------------------------------------------------------------------------
__device__ __forceinline__ float ex2f(float x) {
    float r; asm("ex2.approx.ftz.f32 %0, %1;" : "=f"(r) : "f"(x)); return r;
}
__device__ __forceinline__ float rcpf(float x) {
    float r; asm("rcp.approx.ftz.f32 %0, %1;" : "=f"(r) : "f"(x)); return r;
}
__device__ __forceinline__ float tanh_acc(float x) {
    const float C = 2.885390081777927f;  // 2*log2(e)
    float e = ex2f(fminf(x * C, 30.0f));
    return 1.0f - 2.0f * rcpf(e + 1.0f);
}
// Fast tanh for the scan hot loop: single MUFU.TANH (proven: final err 7e-6).
__device__ __forceinline__ float tanh_fast(float x) {
    float r; asm("tanh.approx.f32 %0, %1;" : "=f"(r) : "f"(x)); return r;
}

// ---------------------------------------------------------------------------
// Packed f32x2 ops (FFMA2 — PTX-only) and pack/unpack movs
// ---------------------------------------------------------------------------
__device__ __forceinline__ u64 pk2(float lo, float hi) {
    u64 r; asm("mov.b64 %0, {%1, %2};" : "=l"(r) : "f"(lo), "f"(hi)); return r;
}
__device__ __forceinline__ void upk2(u64 v, float& lo, float& hi) {
    asm("mov.b64 {%0, %1}, %2;" : "=f"(lo), "=f"(hi) : "l"(v));
}
__device__ __forceinline__ u64 fma2(u64 a, u64 b, u64 c) {
    u64 r; asm("fma.rn.f32x2 %0, %1, %2, %3;" : "=l"(r) : "l"(a), "l"(b), "l"(c)); return r;
}
__device__ __forceinline__ u64 mul2(u64 a, u64 b) {
    u64 r; asm("mul.rn.f32x2 %0, %1, %2;" : "=l"(r) : "l"(a), "l"(b)); return r;
}
__device__ __forceinline__ u64 add2(u64 a, u64 b) {
    u64 r; asm("add.rn.f32x2 %0, %1, %2;" : "=l"(r) : "l"(a), "l"(b)); return r;
}

// ---------------------------------------------------------------------------
// Kernel 1: encoder + sequential Euler scan. (R10 placement + tanh_fast,
// with f32x2-packed math.)
// 8 lanes per batch element, 4 hidden units each. Flat-7 butterfly on the
// PACKED (p0,p1) value: 7 shfl.b64 (one 26-cyc level on the chain), 7 add2.
// 128 blocks x 64 threads -> 256 warps, 1 warp per SMSP across 128 SMs.
// ---------------------------------------------------------------------------
__global__ void __launch_bounds__(64, 1)
scan_kernel(const float* __restrict__ x,
            const float* __restrict__ ew1, const float* __restrict__ eb1,
            const float* __restrict__ ew2, const float* __restrict__ eb2,
            const float* __restrict__ fw1, const float* __restrict__ fb1,
            const float* __restrict__ fw2, const float* __restrict__ fb2,
            float* __restrict__ out)
{
    const int g = blockIdx.x * 64 + threadIdx.x;   // 0..8191
    const int b = g >> 3;                          // batch element
    const int q = g & 7;                           // lane within chain group
    const int j0 = q * 4;                          // first hidden unit

    // --- Packed register-resident ODE weights (natural domain for tanh) ---
    float w1a[4], w1b[4], b1s[4];
#pragma unroll
    for (int i = 0; i < 4; i++) {
        int j = j0 + i;
        w1a[i] = fw1[j];
        w1b[i] = fw1[HH + j];
        b1s[i] = fb1[j];
    }
    const u64 W1A01 = pk2(w1a[0], w1a[1]), W1A23 = pk2(w1a[2], w1a[3]);
    const u64 W1B01 = pk2(w1b[0], w1b[1]), W1B23 = pk2(w1b[2], w1b[3]);
    const u64 B01   = pk2(b1s[0], b1s[1]), B23   = pk2(b1s[2], b1s[3]);
    const u64 W2P0 = pk2(fw2[(j0+0)*PP], fw2[(j0+0)*PP+1]);
    const u64 W2P1 = pk2(fw2[(j0+1)*PP], fw2[(j0+1)*PP+1]);
    const u64 W2P2 = pk2(fw2[(j0+2)*PP], fw2[(j0+2)*PP+1]);
    const u64 W2P3 = pk2(fw2[(j0+3)*PP], fw2[(j0+3)*PP+1]);
    // b2 folded into lane 0's packed accumulation seed
    const u64 SP = (q == 0) ? pk2(fb2[0], fb2[1]) : 0ull;

    // --- Encoder: z0 = tanh(x[b,:30] @ ew1 + eb1) @ ew2 + eb2 (accurate) ---
    float z1, z2;
    {
        float acc0 = 0.f, acc1 = 0.f;
        const float* xb = x + (size_t)b * TT;
#pragma unroll
        for (int i = 0; i < 4; i++) {
            int j = j0 + i;
            float u = eb1[j];
#pragma unroll
            for (int l = 0; l < LL; l++)
                u = fmaf(xb[l], ew1[l * HH + j], u);
            float th = tanh_acc(u);
            acc0 = fmaf(th, ew2[j * PP + 0], acc0);
            acc1 = fmaf(th, ew2[j * PP + 1], acc1);
        }
        acc0 += __shfl_xor_sync(0xffffffffu, acc0, 1);
        acc1 += __shfl_xor_sync(0xffffffffu, acc1, 1);
        acc0 += __shfl_xor_sync(0xffffffffu, acc0, 2);
        acc1 += __shfl_xor_sync(0xffffffffu, acc1, 2);
        acc0 += __shfl_xor_sync(0xffffffffu, acc0, 4);
        acc1 += __shfl_xor_sync(0xffffffffu, acc1, 4);
        z1 = acc0 + eb2[0];
        z2 = acc1 + eb2[1];
    }

    // z region of d_out: after xhat (B*T) and a (B*T*P) -> offset 3*B*T floats.
    float4* zo4 = reinterpret_cast<float4*>(out + 3ull * BB * TT)
                + (size_t)b * (TT / 2);

    // --- One Euler step ---
    auto STEP = [&]() {
        // u pairs via packed FFMA2: u_i = w1a_i*z1 + w1b_i*z2 + b1_i
        u64 zz1 = pk2(z1, z1), zz2 = pk2(z2, z2);
        u64 u01 = fma2(zz1, W1A01, fma2(zz2, W1B01, B01));
        u64 u23 = fma2(zz1, W1A23, fma2(zz2, W1B23, B23));
        float u0, u1, u2, u3;
        upk2(u01, u0, u1); upk2(u23, u2, u3);
        float t0 = tanh_fast(u0);
        float t1 = tanh_fast(u1);
        float t2 = tanh_fast(u2);
        float t3 = tanh_fast(u3);
        // packed w2-apply: p = (p0,p1) = sum_i (w2a_i, w2b_i) * t_i (+b2 seed)
        u64 pa = fma2(pk2(t1, t1), W2P1, fma2(pk2(t0, t0), W2P0, SP));
        u64 pb = fma2(pk2(t3, t3), W2P3, mul2(pk2(t2, t2), W2P2));
        u64 p  = add2(pa, pb);
        // flat butterfly over the 8-lane group on the PACKED value:
        // 7 independent shfl.b64 -> one shuffle latency; adds are add2.
        u64 s1 = __shfl_xor_sync(0xffffffffu, p, 1);
        u64 s2 = __shfl_xor_sync(0xffffffffu, p, 2);
        u64 s3 = __shfl_xor_sync(0xffffffffu, p, 3);
        u64 s4 = __shfl_xor_sync(0xffffffffu, p, 4);
        u64 s5 = __shfl_xor_sync(0xffffffffu, p, 5);
        u64 s6 = __shfl_xor_sync(0xffffffffu, p, 6);
        u64 s7 = __shfl_xor_sync(0xffffffffu, p, 7);
        u64 d = add2(add2(add2(p, s1), add2(s2, s3)),
                     add2(add2(s4, s5), add2(s6, s7)));
        float d0, d1;
        upk2(d, d0, d1);
        z1 += d0;
        z2 += d1;
    };

    // --- 4095 steps, unrolled by 2, one float4 store per 2 time entries ---
#pragma unroll 1
    for (int k = 0; k < 2047; ++k) {
        float az1 = z1, az2 = z2;          // entry 2k
        STEP();                            // entry 2k+1
        if (q == 0) zo4[k] = make_float4(az1, az2, z1, z2);
        STEP();                            // entry 2k+2
    }
    {
        float az1 = z1, az2 = z2;          // entry 4094
        STEP();                            // entry 4095
        if (q == 0) zo4[2047] = make_float4(az1, az2, z1, z2);
    }
}

// ---------------------------------------------------------------------------
// Kernel 2: parallel epilogue. One thread per (b,t). (Accurate tanh.)
// kappa = tanh(z); a = [k1*(1-k2), k2]; xhat[t>=P] = a . phi
// ---------------------------------------------------------------------------
__global__ void __launch_bounds__(256)
post_kernel(const float* __restrict__ phi, float* __restrict__ out)
{
    size_t idx = (size_t)blockIdx.x * blockDim.x + threadIdx.x;  // = b*T + t
    if (idx >= (size_t)BB * TT) return;
    int t = (int)(idx & (TT - 1));

    float2 z = reinterpret_cast<const float2*>(out + 3ull * BB * TT)[idx];
    float k1 = tanh_acc(z.x);
    float k2 = tanh_acc(z.y);
    float a0 = k1 * (1.0f - k2);
    float a1 = k2;
    reinterpret_cast<float2*>(out + 1ull * BB * TT)[idx] = make_float2(a0, a1);

    float xh = 0.0f;
    if (t >= PP) {
        float2 ph = reinterpret_cast<const float2*>(phi)[idx];
        xh = fmaf(a0, ph.x, a1 * ph.y);
    }
    out[idx] = xh;
}

// ---------------------------------------------------------------------------
extern "C" void kernel_launch(void* const* d_in, const int* in_sizes, int n_in,
                              void* d_out, int out_size)
{
    const float* x   = (const float*)d_in[0];
    const float* phi = (const float*)d_in[1];
    const float* ew1 = (const float*)d_in[2];
    const float* eb1 = (const float*)d_in[3];
    const float* ew2 = (const float*)d_in[4];
    const float* eb2 = (const float*)d_in[5];
    const float* fw1 = (const float*)d_in[6];
    const float* fb1 = (const float*)d_in[7];
    const float* fw2 = (const float*)d_in[8];
    const float* fb2 = (const float*)d_in[9];
    float* out = (float*)d_out;

    // Scan: 8192 threads = 8 lanes per chain; 128 blocks x 64 threads
    // -> 256 warps, one per SMSP across 128 SMs. (Proven placement.)
    scan_kernel<<<128, 64>>>(x, ew1, eb1, ew2, eb2, fw1, fb1, fw2, fb2, out);

    // Epilogue: one thread per (b,t)
    int nblk = (BB * TT) / 256;
    post_kernel<<<nblk, 256>>>(phi, out);
}